// round 6
// baseline (speedup 1.0000x reference)
#include <cuda_runtime.h>
#include <mma.h>
#include <cmath>

using namespace nvcuda;

#define BATCH 16
#define SEQL  512
#define DIMC  2048
#define NHEAD 16
#define HDIM  128
#define NQKV  6144
#define MTOT  (BATCH*SEQL)   // 8192

// Scratch (device globals: allocation-guard safe)
__device__ float g_q[(size_t)BATCH*NHEAD*SEQL*HDIM];  // [B,H,T,hd]
__device__ float g_k[(size_t)BATCH*NHEAD*SEQL*HDIM];
__device__ float g_v[(size_t)BATCH*NHEAD*SEQL*HDIM];
__device__ float g_y[(size_t)MTOT*DIMC];              // attention out, [B*T, C]

// ---------------------------------------------------------------------------
// TF32 GEMM, double-buffered, 128x256 CTA tile, 64x64 warp tiles (8 warps)
// ---------------------------------------------------------------------------
#define BM 128
#define BN 256
#define BK 32
#define ALD (BK + 4)    // 36
#define BLD (BN + 4)    // 260
#define GEMM_SMEM ((2*BM*ALD + 2*BK*BLD) * 4)   // 103424 B

template<int MODE>
__global__ void __launch_bounds__(256, 1)
gemm_tf32_kernel(const float* __restrict__ A, const float* __restrict__ Bmat,
                 float* __restrict__ Cout, int N)
{
    extern __shared__ float sm[];
    float* As = sm;                       // [2][BM][ALD]
    float* Bs = sm + 2 * BM * ALD;        // [2][BK][BLD]

    const int tid  = threadIdx.x;
    const int warp = tid >> 5;
    const int wm   = warp >> 2;      // 0..1  (rows of 64)
    const int wn   = warp & 3;       // 0..3  (cols of 64)
    const int tileM = blockIdx.y * BM;
    const int tileN = blockIdx.x * BN;

    const float* Aptr = (MODE == 1) ? g_y : A;

    const int arow = tid >> 3;
    const int ac   = (tid & 7) * 4;
    const int brow = tid >> 6;
    const int bc   = (tid & 63) * 4;

    wmma::fragment<wmma::accumulator, 16, 16, 8, float> acc[4][4];
#pragma unroll
    for (int i = 0; i < 4; i++)
#pragma unroll
        for (int j = 0; j < 4; j++) wmma::fill_fragment(acc[i][j], 0.0f);

    float4 ra[4], rb[8];

#define LOAD_TILES(k0)                                                          \
    {                                                                           \
        _Pragma("unroll")                                                       \
        for (int it = 0; it < 4; it++)                                          \
            ra[it] = *(const float4*)(Aptr + (size_t)(tileM + arow + it*32) * DIMC + (k0) + ac); \
        _Pragma("unroll")                                                       \
        for (int it = 0; it < 8; it++)                                          \
            rb[it] = *(const float4*)(Bmat + (size_t)((k0) + brow + it*4) * N + tileN + bc); \
    }

#define STORE_TILES(st)                                                         \
    {                                                                           \
        _Pragma("unroll")                                                       \
        for (int it = 0; it < 4; it++) {                                        \
            float* d = &As[(size_t)(st) * BM * ALD + (arow + it*32) * ALD + ac]; \
            d[0] = wmma::__float_to_tf32(ra[it].x);                             \
            d[1] = wmma::__float_to_tf32(ra[it].y);                             \
            d[2] = wmma::__float_to_tf32(ra[it].z);                             \
            d[3] = wmma::__float_to_tf32(ra[it].w);                             \
        }                                                                       \
        _Pragma("unroll")                                                       \
        for (int it = 0; it < 8; it++) {                                        \
            float* e = &Bs[(size_t)(st) * BK * BLD + (brow + it*4) * BLD + bc]; \
            e[0] = wmma::__float_to_tf32(rb[it].x);                             \
            e[1] = wmma::__float_to_tf32(rb[it].y);                             \
            e[2] = wmma::__float_to_tf32(rb[it].z);                             \
            e[3] = wmma::__float_to_tf32(rb[it].w);                             \
        }                                                                       \
    }

#define COMPUTE(st)                                                             \
    {                                                                           \
        const float* Ab = &As[(size_t)(st) * BM * ALD];                         \
        const float* Bb = &Bs[(size_t)(st) * BK * BLD];                         \
        _Pragma("unroll")                                                       \
        for (int ks = 0; ks < 4; ks++) {                                        \
            wmma::fragment<wmma::matrix_a, 16, 16, 8, wmma::precision::tf32, wmma::row_major> af[4]; \
            wmma::fragment<wmma::matrix_b, 16, 16, 8, wmma::precision::tf32, wmma::row_major> bf[4]; \
            _Pragma("unroll")                                                   \
            for (int i = 0; i < 4; i++)                                         \
                wmma::load_matrix_sync(af[i], Ab + (wm*64 + i*16) * ALD + ks*8, ALD); \
            _Pragma("unroll")                                                   \
            for (int j = 0; j < 4; j++)                                         \
                wmma::load_matrix_sync(bf[j], Bb + (ks*8) * BLD + wn*64 + j*16, BLD); \
            _Pragma("unroll")                                                   \
            for (int i = 0; i < 4; i++)                                         \
                _Pragma("unroll")                                               \
                for (int j = 0; j < 4; j++)                                     \
                    wmma::mma_sync(acc[i][j], af[i], bf[j], acc[i][j]);         \
        }                                                                       \
    }

    LOAD_TILES(0);
    STORE_TILES(0);
    __syncthreads();

    int cur = 0;
    for (int k0 = BK; k0 < DIMC; k0 += BK) {
        LOAD_TILES(k0);
        COMPUTE(cur);
        STORE_TILES(cur ^ 1);
        __syncthreads();
        cur ^= 1;
    }
    COMPUTE(cur);

#undef LOAD_TILES
#undef STORE_TILES
#undef COMPUTE

    if (MODE == 1) {
#pragma unroll
        for (int i = 0; i < 4; i++)
#pragma unroll
            for (int j = 0; j < 4; j++) {
                float* cptr = Cout + (size_t)(tileM + wm * 64 + i * 16) * N
                                   + tileN + wn * 64 + j * 16;
                wmma::store_matrix_sync(cptr, acc[i][j], N, wmma::mem_row_major);
            }
    } else {
        int colw  = tileN + wn * 64;
        int nb128 = colw >> 7;
        int which = nb128 >> 4;
        int h     = nb128 & 15;
        int cin   = colw & 127;
        int b     = tileM / SEQL;
        int t0    = tileM % SEQL;
        float* dstbase = (which == 0 ? g_q : (which == 1 ? g_k : g_v))
                       + (size_t)((b * NHEAD + h) * SEQL + t0 + wm * 64) * HDIM + cin;
#pragma unroll
        for (int i = 0; i < 4; i++)
#pragma unroll
            for (int j = 0; j < 4; j++) {
                float* cptr = dstbase + (size_t)(i * 16) * HDIM + j * 16;
                wmma::store_matrix_sync(cptr, acc[i][j], HDIM, wmma::mem_row_major);
            }
    }
}

// ---------------------------------------------------------------------------
// RoPE in-place on q and k: first 16 dims of each head, pairs (p, p+8)
// ---------------------------------------------------------------------------
__global__ void rope_kernel()
{
    int i = blockIdx.x * blockDim.x + threadIdx.x;
    const int per = BATCH * NHEAD * SEQL * 8;
    if (i >= 2 * per) return;
    int which = i / per;
    int r  = i % per;
    int bh = r / (SEQL * 8);
    int t  = (r / 8) % SEQL;
    int p  = r & 7;

    float inv = powf(10000.0f, -(float)p / 8.0f);
    float ang = (float)t * inv;
    float c = cosf(ang), s = sinf(ang);

    float* base = (which ? g_k : g_q) + (size_t)(bh * SEQL + t) * HDIM;
    float x1 = base[p];
    float x2 = base[p + 8];
    base[p]     = x1 * c - x2 * s;
    base[p + 8] = x2 * c + x1 * s;
}

// ---------------------------------------------------------------------------
// Causal flash attention, fp32 SIMT. BQ=BK=64, 256 threads.
// Warp w owns q-rows [8w,8w+8); lane l owns S cols {l,l+32}, dims [4l,4l+4).
// PsT transposed [col][row] (stride 68) -> PV uses broadcast float4 loads.
// ---------------------------------------------------------------------------
#define AQ 64
#define AK 64
#define KTLD 65    // padded ld of transposed K
#define PTLD 68    // PsT stride (multiple of 4 for aligned float4)

__global__ void __launch_bounds__(256)
attn_kernel(float* __restrict__ Y)
{
    extern __shared__ float smattn[];
    float* Qs  = smattn;                    // 64*128
    float* Kt  = Qs + AQ * HDIM;            // 128*65 (transposed K)
    float* Vs  = Kt + HDIM * KTLD;          // 64*128
    float* PsT = Vs + AK * HDIM;            // 64 cols * 68

    const int tid = threadIdx.x;
    const int w   = tid >> 5;
    const int l   = tid & 31;
    const int bh  = blockIdx.y;
    const int qblk = blockIdx.x;
    const float scale = 0.08838834764831845f;   // 1/sqrt(128)

    const float* Qg = g_q + (size_t)bh * SEQL * HDIM;
    const float* Kg = g_k + (size_t)bh * SEQL * HDIM;
    const float* Vg = g_v + (size_t)bh * SEQL * HDIM;

#pragma unroll
    for (int it = 0; it < 8; it++) {
        int idx = tid + it * 256;
        int row = idx >> 5;
        int c4  = idx & 31;
        float4 v = *(const float4*)(Qg + (size_t)(qblk * AQ + row) * HDIM + c4 * 4);
        v.x *= scale; v.y *= scale; v.z *= scale; v.w *= scale;
        *(float4*)&Qs[row * HDIM + c4 * 4] = v;
    }

    float o[8][4];
    float mr[8], lr[8];
#pragma unroll
    for (int r = 0; r < 8; r++) {
        mr[r] = -INFINITY; lr[r] = 0.0f;
        o[r][0] = o[r][1] = o[r][2] = o[r][3] = 0.0f;
    }

    for (int j = 0; j <= qblk; j++) {
        __syncthreads();
#pragma unroll
        for (int it = 0; it < 8; it++) {
            int idx = tid + it * 256;
            int col = idx >> 5;
            int c4  = idx & 31;
            int kk  = c4 * 4;
            float4 kv = *(const float4*)(Kg + (size_t)(j * AK + col) * HDIM + kk);
            Kt[(kk + 0) * KTLD + col] = kv.x;
            Kt[(kk + 1) * KTLD + col] = kv.y;
            Kt[(kk + 2) * KTLD + col] = kv.z;
            Kt[(kk + 3) * KTLD + col] = kv.w;
            float4 vv = *(const float4*)(Vg + (size_t)(j * AK + col) * HDIM + kk);
            *(float4*)&Vs[col * HDIM + kk] = vv;
        }
        __syncthreads();

        // --- S = Q K^T (8 rows x 2 cols per thread), unrolled for ILP ---
        float s0[8], s1[8];
#pragma unroll
        for (int r = 0; r < 8; r++) { s0[r] = 0.0f; s1[r] = 0.0f; }
#pragma unroll 4
        for (int kk = 0; kk < HDIM; kk += 4) {
            float ka[4], kb[4];
#pragma unroll
            for (int u = 0; u < 4; u++) {
                ka[u] = Kt[(kk + u) * KTLD + l];
                kb[u] = Kt[(kk + u) * KTLD + l + 32];
            }
#pragma unroll
            for (int r = 0; r < 8; r++) {
                float4 qv = *(const float4*)&Qs[(w * 8 + r) * HDIM + kk];
                s0[r] += qv.x * ka[0] + qv.y * ka[1] + qv.z * ka[2] + qv.w * ka[3];
                s1[r] += qv.x * kb[0] + qv.y * kb[1] + qv.z * kb[2] + qv.w * kb[3];
            }
        }

        if (j == qblk) {
#pragma unroll
            for (int r = 0; r < 8; r++) {
                int row = w * 8 + r;
                if (l > row)      s0[r] = -1e30f;
                if (l + 32 > row) s1[r] = -1e30f;
            }
        }

        // --- online softmax; P stored transposed [col][row] ---
#pragma unroll
        for (int r = 0; r < 8; r++) {
            float mx = fmaxf(s0[r], s1[r]);
#pragma unroll
            for (int off = 16; off; off >>= 1)
                mx = fmaxf(mx, __shfl_xor_sync(0xffffffffu, mx, off));
            float mnew  = fmaxf(mr[r], mx);
            float alpha = __expf(mr[r] - mnew);
            float p0 = __expf(s0[r] - mnew);
            float p1 = __expf(s1[r] - mnew);
            float rs = p0 + p1;
#pragma unroll
            for (int off = 16; off; off >>= 1)
                rs += __shfl_xor_sync(0xffffffffu, rs, off);
            lr[r] = lr[r] * alpha + rs;
            mr[r] = mnew;
            o[r][0] *= alpha; o[r][1] *= alpha; o[r][2] *= alpha; o[r][3] *= alpha;
            PsT[l * PTLD        + w * 8 + r] = p0;
            PsT[(l + 32) * PTLD + w * 8 + r] = p1;
        }
        __syncwarp();

        // --- O += P V : broadcast float4 P loads + V float4, unrolled ---
#pragma unroll 4
        for (int col = 0; col < AK; col++) {
            float4 pa = *(const float4*)&PsT[col * PTLD + w * 8];
            float4 pb = *(const float4*)&PsT[col * PTLD + w * 8 + 4];
            float4 vv = *(const float4*)&Vs[col * HDIM + 4 * l];
            o[0][0] += pa.x * vv.x; o[0][1] += pa.x * vv.y; o[0][2] += pa.x * vv.z; o[0][3] += pa.x * vv.w;
            o[1][0] += pa.y * vv.x; o[1][1] += pa.y * vv.y; o[1][2] += pa.y * vv.z; o[1][3] += pa.y * vv.w;
            o[2][0] += pa.z * vv.x; o[2][1] += pa.z * vv.y; o[2][2] += pa.z * vv.z; o[2][3] += pa.z * vv.w;
            o[3][0] += pa.w * vv.x; o[3][1] += pa.w * vv.y; o[3][2] += pa.w * vv.z; o[3][3] += pa.w * vv.w;
            o[4][0] += pb.x * vv.x; o[4][1] += pb.x * vv.y; o[4][2] += pb.x * vv.z; o[4][3] += pb.x * vv.w;
            o[5][0] += pb.y * vv.x; o[5][1] += pb.y * vv.y; o[5][2] += pb.y * vv.z; o[5][3] += pb.y * vv.w;
            o[6][0] += pb.z * vv.x; o[6][1] += pb.z * vv.y; o[6][2] += pb.z * vv.z; o[6][3] += pb.z * vv.w;
            o[7][0] += pb.w * vv.x; o[7][1] += pb.w * vv.y; o[7][2] += pb.w * vv.z; o[7][3] += pb.w * vv.w;
        }
    }

    int b = bh >> 4, h = bh & 15;
#pragma unroll
    for (int r = 0; r < 8; r++) {
        float inv = 1.0f / lr[r];
        int t = qblk * AQ + w * 8 + r;
        float4 ov;
        ov.x = o[r][0] * inv; ov.y = o[r][1] * inv;
        ov.z = o[r][2] * inv; ov.w = o[r][3] * inv;
        *(float4*)(Y + (size_t)(b * SEQL + t) * DIMC + h * HDIM + 4 * l) = ov;
    }
}

#define ATTN_SMEM ((AQ*HDIM + HDIM*KTLD + AK*HDIM + AK*PTLD) * 4)

// ---------------------------------------------------------------------------
extern "C" void kernel_launch(void* const* d_in, const int* in_sizes, int n_in,
                              void* d_out, int out_size)
{
    const float* x    = (const float*)d_in[0];   // [16,512,2048]
    const float* Wqkv = (const float*)d_in[1];   // [2048,6144]
    const float* Wout = (const float*)d_in[2];   // [2048,2048]
    float* out = (float*)d_out;                  // [16,512,2048]

    static bool attrs_set = false;
    if (!attrs_set) {
        cudaFuncSetAttribute(gemm_tf32_kernel<0>, cudaFuncAttributeMaxDynamicSharedMemorySize, GEMM_SMEM);
        cudaFuncSetAttribute(gemm_tf32_kernel<1>, cudaFuncAttributeMaxDynamicSharedMemorySize, GEMM_SMEM);
        cudaFuncSetAttribute(attn_kernel, cudaFuncAttributeMaxDynamicSharedMemorySize, ATTN_SMEM);
        attrs_set = true;
    }

    // 1) QKV GEMM with fused scatter to [B,H,T,hd]
    gemm_tf32_kernel<0><<<dim3(NQKV / BN, MTOT / BM), 256, GEMM_SMEM>>>(x, Wqkv, nullptr, NQKV);

    // 2) RoPE on q,k (first 16 dims)
    {
        int total = 2 * BATCH * NHEAD * SEQL * 8;
        rope_kernel<<<(total + 255) / 256, 256>>>();
    }

    // 3) Causal flash attention (SIMT fp32)
    {
        float* yp = nullptr;
        cudaGetSymbolAddress((void**)&yp, g_y);
        attn_kernel<<<dim3(SEQL / AQ, BATCH * NHEAD), 256, ATTN_SMEM>>>(yp);
    }

    // 4) Output projection
    gemm_tf32_kernel<1><<<dim3(DIMC / BN, MTOT / BM), 256, GEMM_SMEM>>>(nullptr, Wout, out, DIMC);
}

// round 7
// speedup vs baseline: 1.0293x; 1.0293x over previous
#include <cuda_runtime.h>
#include <mma.h>
#include <cmath>

using namespace nvcuda;

#define BATCH 16
#define SEQL  512
#define DIMC  2048
#define NHEAD 16
#define HDIM  128
#define NQKV  6144
#define MTOT  (BATCH*SEQL)   // 8192

// Scratch (device globals: allocation-guard safe)
__device__ float g_q[(size_t)BATCH*NHEAD*SEQL*HDIM];  // [B,H,T,hd]
__device__ float g_k[(size_t)BATCH*NHEAD*SEQL*HDIM];
__device__ float g_v[(size_t)BATCH*NHEAD*SEQL*HDIM];
__device__ float g_y[(size_t)MTOT*DIMC];              // attention out, [B*T, C]

// ---------------------------------------------------------------------------
// TF32 GEMM, double-buffered, 128x256 CTA tile, 64x64 warp tiles (8 warps)
// ---------------------------------------------------------------------------
#define BM 128
#define BN 256
#define BK 32
#define ALD (BK + 4)    // 36
#define BLD (BN + 4)    // 260
#define GEMM_SMEM ((2*BM*ALD + 2*BK*BLD) * 4)   // 103424 B

template<int MODE>
__global__ void __launch_bounds__(256, 1)
gemm_tf32_kernel(const float* __restrict__ A, const float* __restrict__ Bmat,
                 float* __restrict__ Cout, int N)
{
    extern __shared__ float sm[];
    float* As = sm;                       // [2][BM][ALD]
    float* Bs = sm + 2 * BM * ALD;        // [2][BK][BLD]

    const int tid  = threadIdx.x;
    const int warp = tid >> 5;
    const int wm   = warp >> 2;      // 0..1  (rows of 64)
    const int wn   = warp & 3;       // 0..3  (cols of 64)
    const int tileM = blockIdx.y * BM;
    const int tileN = blockIdx.x * BN;

    const float* Aptr = (MODE == 1) ? g_y : A;

    const int arow = tid >> 3;
    const int ac   = (tid & 7) * 4;
    const int brow = tid >> 6;
    const int bc   = (tid & 63) * 4;

    wmma::fragment<wmma::accumulator, 16, 16, 8, float> acc[4][4];
#pragma unroll
    for (int i = 0; i < 4; i++)
#pragma unroll
        for (int j = 0; j < 4; j++) wmma::fill_fragment(acc[i][j], 0.0f);

    float4 ra[4], rb[8];

#define LOAD_TILES(k0)                                                          \
    {                                                                           \
        _Pragma("unroll")                                                       \
        for (int it = 0; it < 4; it++)                                          \
            ra[it] = *(const float4*)(Aptr + (size_t)(tileM + arow + it*32) * DIMC + (k0) + ac); \
        _Pragma("unroll")                                                       \
        for (int it = 0; it < 8; it++)                                          \
            rb[it] = *(const float4*)(Bmat + (size_t)((k0) + brow + it*4) * N + tileN + bc); \
    }

#define STORE_TILES(st)                                                         \
    {                                                                           \
        _Pragma("unroll")                                                       \
        for (int it = 0; it < 4; it++) {                                        \
            float* d = &As[(size_t)(st) * BM * ALD + (arow + it*32) * ALD + ac]; \
            d[0] = wmma::__float_to_tf32(ra[it].x);                             \
            d[1] = wmma::__float_to_tf32(ra[it].y);                             \
            d[2] = wmma::__float_to_tf32(ra[it].z);                             \
            d[3] = wmma::__float_to_tf32(ra[it].w);                             \
        }                                                                       \
        _Pragma("unroll")                                                       \
        for (int it = 0; it < 8; it++) {                                        \
            float* e = &Bs[(size_t)(st) * BK * BLD + (brow + it*4) * BLD + bc]; \
            e[0] = wmma::__float_to_tf32(rb[it].x);                             \
            e[1] = wmma::__float_to_tf32(rb[it].y);                             \
            e[2] = wmma::__float_to_tf32(rb[it].z);                             \
            e[3] = wmma::__float_to_tf32(rb[it].w);                             \
        }                                                                       \
    }

#define COMPUTE(st)                                                             \
    {                                                                           \
        const float* Ab = &As[(size_t)(st) * BM * ALD];                         \
        const float* Bb = &Bs[(size_t)(st) * BK * BLD];                         \
        _Pragma("unroll")                                                       \
        for (int ks = 0; ks < 4; ks++) {                                        \
            wmma::fragment<wmma::matrix_a, 16, 16, 8, wmma::precision::tf32, wmma::row_major> af[4]; \
            wmma::fragment<wmma::matrix_b, 16, 16, 8, wmma::precision::tf32, wmma::row_major> bf[4]; \
            _Pragma("unroll")                                                   \
            for (int i = 0; i < 4; i++)                                         \
                wmma::load_matrix_sync(af[i], Ab + (wm*64 + i*16) * ALD + ks*8, ALD); \
            _Pragma("unroll")                                                   \
            for (int j = 0; j < 4; j++)                                         \
                wmma::load_matrix_sync(bf[j], Bb + (ks*8) * BLD + wn*64 + j*16, BLD); \
            _Pragma("unroll")                                                   \
            for (int i = 0; i < 4; i++)                                         \
                _Pragma("unroll")                                               \
                for (int j = 0; j < 4; j++)                                     \
                    wmma::mma_sync(acc[i][j], af[i], bf[j], acc[i][j]);         \
        }                                                                       \
    }

    LOAD_TILES(0);
    STORE_TILES(0);
    __syncthreads();

    int cur = 0;
    for (int k0 = BK; k0 < DIMC; k0 += BK) {
        LOAD_TILES(k0);
        COMPUTE(cur);
        STORE_TILES(cur ^ 1);
        __syncthreads();
        cur ^= 1;
    }
    COMPUTE(cur);

#undef LOAD_TILES
#undef STORE_TILES
#undef COMPUTE

    if (MODE == 1) {
#pragma unroll
        for (int i = 0; i < 4; i++)
#pragma unroll
            for (int j = 0; j < 4; j++) {
                float* cptr = Cout + (size_t)(tileM + wm * 64 + i * 16) * N
                                   + tileN + wn * 64 + j * 16;
                wmma::store_matrix_sync(cptr, acc[i][j], N, wmma::mem_row_major);
            }
    } else {
        int colw  = tileN + wn * 64;
        int nb128 = colw >> 7;
        int which = nb128 >> 4;
        int h     = nb128 & 15;
        int cin   = colw & 127;
        int b     = tileM / SEQL;
        int t0    = tileM % SEQL;
        float* dstbase = (which == 0 ? g_q : (which == 1 ? g_k : g_v))
                       + (size_t)((b * NHEAD + h) * SEQL + t0 + wm * 64) * HDIM + cin;
#pragma unroll
        for (int i = 0; i < 4; i++)
#pragma unroll
            for (int j = 0; j < 4; j++) {
                float* cptr = dstbase + (size_t)(i * 16) * HDIM + j * 16;
                wmma::store_matrix_sync(cptr, acc[i][j], HDIM, wmma::mem_row_major);
            }
    }
}

// ---------------------------------------------------------------------------
// RoPE in-place on q and k: first 16 dims of each head, pairs (p, p+8)
// ---------------------------------------------------------------------------
__global__ void rope_kernel()
{
    int i = blockIdx.x * blockDim.x + threadIdx.x;
    const int per = BATCH * NHEAD * SEQL * 8;
    if (i >= 2 * per) return;
    int which = i / per;
    int r  = i % per;
    int bh = r / (SEQL * 8);
    int t  = (r / 8) % SEQL;
    int p  = r & 7;

    float inv = powf(10000.0f, -(float)p / 8.0f);
    float ang = (float)t * inv;
    float c = cosf(ang), s = sinf(ang);

    float* base = (which ? g_k : g_q) + (size_t)(bh * SEQL + t) * HDIM;
    float x1 = base[p];
    float x2 = base[p + 8];
    base[p]     = x1 * c - x2 * s;
    base[p + 8] = x2 * c + x1 * s;
}

// ---------------------------------------------------------------------------
// Causal flash attention, fp32 SIMT. BQ=BK=64, 256 threads, 2 CTAs/SM.
// V is NOT staged in smem: PV reads g_v directly (coalesced, L1-resident).
// smem = Qs(32K) + Kt(33.3K) + Ps(16K) = 82.4KB -> 2 CTAs/SM.
// ---------------------------------------------------------------------------
#define AQ 64
#define AK 64
#define KTLD 65   // padded ld of transposed K (needed for conflict-free stores)
#define ATTN_SMEM ((AQ*HDIM + HDIM*KTLD + AQ*AK) * 4)

__global__ void __launch_bounds__(256, 2)
attn_kernel(float* __restrict__ Y)
{
    extern __shared__ float smattn[];
    float* Qs = smattn;                    // 64*128
    float* Kt = Qs + AQ * HDIM;            // 128*65 (transposed K)
    float* Ps = Kt + HDIM * KTLD;          // 64*64

    const int tid = threadIdx.x;
    const int w   = tid >> 5;
    const int l   = tid & 31;
    const int bh  = blockIdx.y;            // 0..255
    const int qblk = blockIdx.x;           // 0..7
    const float scale = 0.08838834764831845f;   // 1/sqrt(128)

    const float* Qg = g_q + (size_t)bh * SEQL * HDIM;
    const float* Kg = g_k + (size_t)bh * SEQL * HDIM;
    const float* Vg = g_v + (size_t)bh * SEQL * HDIM;

#pragma unroll
    for (int it = 0; it < 8; it++) {
        int idx = tid + it * 256;
        int row = idx >> 5;
        int c4  = idx & 31;
        float4 v = *(const float4*)(Qg + (size_t)(qblk * AQ + row) * HDIM + c4 * 4);
        v.x *= scale; v.y *= scale; v.z *= scale; v.w *= scale;
        *(float4*)&Qs[row * HDIM + c4 * 4] = v;
    }

    float o[8][4];
    float mr[8], lr[8];
#pragma unroll
    for (int r = 0; r < 8; r++) {
        mr[r] = -INFINITY; lr[r] = 0.0f;
        o[r][0] = o[r][1] = o[r][2] = o[r][3] = 0.0f;
    }

    for (int j = 0; j <= qblk; j++) {
        __syncthreads();   // previous iter done with Kt
        // Stage K (transposed) only; V stays in global (L1-resident)
#pragma unroll
        for (int it = 0; it < 8; it++) {
            int idx = tid + it * 256;
            int col = idx >> 5;
            int c4  = idx & 31;
            int kk  = c4 * 4;
            float4 kv = *(const float4*)(Kg + (size_t)(j * AK + col) * HDIM + kk);
            Kt[(kk + 0) * KTLD + col] = kv.x;
            Kt[(kk + 1) * KTLD + col] = kv.y;
            Kt[(kk + 2) * KTLD + col] = kv.z;
            Kt[(kk + 3) * KTLD + col] = kv.w;
        }
        __syncthreads();

        // S = Q K^T (8 rows x 2 cols per thread)
        float s0[8], s1[8];
#pragma unroll
        for (int r = 0; r < 8; r++) { s0[r] = 0.0f; s1[r] = 0.0f; }
        for (int kk = 0; kk < HDIM; kk += 4) {
            float ka[4], kb[4];
#pragma unroll
            for (int u = 0; u < 4; u++) {
                ka[u] = Kt[(kk + u) * KTLD + l];
                kb[u] = Kt[(kk + u) * KTLD + l + 32];
            }
#pragma unroll
            for (int r = 0; r < 8; r++) {
                float4 qv = *(const float4*)&Qs[(w * 8 + r) * HDIM + kk];
                s0[r] += qv.x * ka[0] + qv.y * ka[1] + qv.z * ka[2] + qv.w * ka[3];
                s1[r] += qv.x * kb[0] + qv.y * kb[1] + qv.z * kb[2] + qv.w * kb[3];
            }
        }

        if (j == qblk) {
#pragma unroll
            for (int r = 0; r < 8; r++) {
                int row = w * 8 + r;
                if (l > row)      s0[r] = -1e30f;
                if (l + 32 > row) s1[r] = -1e30f;
            }
        }

        // online softmax
#pragma unroll
        for (int r = 0; r < 8; r++) {
            float mx = fmaxf(s0[r], s1[r]);
#pragma unroll
            for (int off = 16; off; off >>= 1)
                mx = fmaxf(mx, __shfl_xor_sync(0xffffffffu, mx, off));
            float mnew  = fmaxf(mr[r], mx);
            float alpha = __expf(mr[r] - mnew);
            float p0 = __expf(s0[r] - mnew);
            float p1 = __expf(s1[r] - mnew);
            float rs = p0 + p1;
#pragma unroll
            for (int off = 16; off; off >>= 1)
                rs += __shfl_xor_sync(0xffffffffu, rs, off);
            lr[r] = lr[r] * alpha + rs;
            mr[r] = mnew;
            o[r][0] *= alpha; o[r][1] *= alpha; o[r][2] *= alpha; o[r][3] *= alpha;
            Ps[(w * 8 + r) * AK + l]      = p0;
            Ps[(w * 8 + r) * AK + l + 32] = p1;
        }
        __syncwarp();

        // O += P V  (V straight from global: coalesced float4 per lane)
        const float* Vrow = Vg + (size_t)(j * AK) * HDIM + 4 * l;
#pragma unroll 4
        for (int col = 0; col < AK; col++) {
            float4 vv = __ldg((const float4*)(Vrow + (size_t)col * HDIM));
#pragma unroll
            for (int r = 0; r < 8; r++) {
                float p = Ps[(w * 8 + r) * AK + col];
                o[r][0] += p * vv.x;
                o[r][1] += p * vv.y;
                o[r][2] += p * vv.z;
                o[r][3] += p * vv.w;
            }
        }
    }

    int b = bh >> 4, h = bh & 15;
#pragma unroll
    for (int r = 0; r < 8; r++) {
        float inv = 1.0f / lr[r];
        int t = qblk * AQ + w * 8 + r;
        float4 ov;
        ov.x = o[r][0] * inv; ov.y = o[r][1] * inv;
        ov.z = o[r][2] * inv; ov.w = o[r][3] * inv;
        *(float4*)(Y + (size_t)(b * SEQL + t) * DIMC + h * HDIM + 4 * l) = ov;
    }
}

// ---------------------------------------------------------------------------
extern "C" void kernel_launch(void* const* d_in, const int* in_sizes, int n_in,
                              void* d_out, int out_size)
{
    const float* x    = (const float*)d_in[0];   // [16,512,2048]
    const float* Wqkv = (const float*)d_in[1];   // [2048,6144]
    const float* Wout = (const float*)d_in[2];   // [2048,2048]
    float* out = (float*)d_out;                  // [16,512,2048]

    static bool attrs_set = false;
    if (!attrs_set) {
        cudaFuncSetAttribute(gemm_tf32_kernel<0>, cudaFuncAttributeMaxDynamicSharedMemorySize, GEMM_SMEM);
        cudaFuncSetAttribute(gemm_tf32_kernel<1>, cudaFuncAttributeMaxDynamicSharedMemorySize, GEMM_SMEM);
        cudaFuncSetAttribute(attn_kernel, cudaFuncAttributeMaxDynamicSharedMemorySize, ATTN_SMEM);
        attrs_set = true;
    }

    // 1) QKV GEMM with fused scatter to [B,H,T,hd]
    gemm_tf32_kernel<0><<<dim3(NQKV / BN, MTOT / BM), 256, GEMM_SMEM>>>(x, Wqkv, nullptr, NQKV);

    // 2) RoPE on q,k (first 16 dims)
    {
        int total = 2 * BATCH * NHEAD * SEQL * 8;
        rope_kernel<<<(total + 255) / 256, 256>>>();
    }

    // 3) Causal flash attention (SIMT fp32, V from global, 2 CTAs/SM)
    {
        float* yp = nullptr;
        cudaGetSymbolAddress((void**)&yp, g_y);
        attn_kernel<<<dim3(SEQL / AQ, BATCH * NHEAD), 256, ATTN_SMEM>>>(yp);
    }

    // 4) Output projection
    gemm_tf32_kernel<1><<<dim3(DIMC / BN, MTOT / BM), 256, GEMM_SMEM>>>(nullptr, Wout, out, DIMC);
}

// round 9
// speedup vs baseline: 2.4303x; 2.3610x over previous
#include <cuda_runtime.h>
#include <mma.h>
#include <cuda_fp16.h>
#include <cmath>

using namespace nvcuda;

#define BATCH 16
#define SEQL  512
#define DIMC  2048
#define NHEAD 16
#define HDIM  128
#define NQKV  6144
#define MTOT  (BATCH*SEQL)   // 8192

// Scratch (device globals: allocation-guard safe)
__device__ float g_q[(size_t)BATCH*NHEAD*SEQL*HDIM];  // [B,H,T,hd]
__device__ float g_k[(size_t)BATCH*NHEAD*SEQL*HDIM];
__device__ float g_v[(size_t)BATCH*NHEAD*SEQL*HDIM];
__device__ float g_y[(size_t)MTOT*DIMC];              // attention out, [B*T, C]

// ---------------------------------------------------------------------------
// FP16 GEMM (fp32 accumulate), double-buffered, 128x256 CTA, 64x64 warp tiles
// C[M,N] = A[M,2048] * B[2048,N];  A,B rounded to fp16 (10-bit mantissa = tf32)
// MODE 0: A = x, N=6144, epilogue scatters q/k/v into [B,H,T,hd] layout
// MODE 1: A = g_y, N=2048, epilogue writes Cout row-major
// ---------------------------------------------------------------------------
#define BM 128
#define BN 256
#define BK 32
#define ALD 40     // halfs; 80B row stride (16B multiple, ldsm conflict-free)
#define BLD 264    // halfs; 528B row stride (16B multiple)
#define GEMM_SMEM ((2*BM*ALD + 2*BK*BLD) * 2)   // 54272 B

template<int MODE>
__global__ void __launch_bounds__(256, 1)
gemm_fp16_kernel(const float* __restrict__ A, const float* __restrict__ Bmat,
                 float* __restrict__ Cout, int N)
{
    extern __shared__ __half sm[];
    __half* As = sm;                       // [2][BM][ALD]
    __half* Bs = sm + 2 * BM * ALD;        // [2][BK][BLD]

    const int tid  = threadIdx.x;
    const int warp = tid >> 5;
    const int wm   = warp >> 2;      // 0..1  (rows of 64)
    const int wn   = warp & 3;       // 0..3  (cols of 64)
    const int tileM = blockIdx.y * BM;
    const int tileN = blockIdx.x * BN;

    const float* Aptr = (MODE == 1) ? g_y : A;

    const int arow = tid >> 3;       // 0..31 base row (stride 32 over 4 its)
    const int ac   = (tid & 7) * 4;  // half-index col
    const int brow = tid >> 6;       // 0..3 base row (stride 4 over 8 its)
    const int bc   = (tid & 63) * 4;

    wmma::fragment<wmma::accumulator, 16, 16, 16, float> acc[4][4];
#pragma unroll
    for (int i = 0; i < 4; i++)
#pragma unroll
        for (int j = 0; j < 4; j++) wmma::fill_fragment(acc[i][j], 0.0f);

    float4 ra[4], rb[8];

#define LOAD_TILES(k0)                                                          \
    {                                                                           \
        _Pragma("unroll")                                                       \
        for (int it = 0; it < 4; it++)                                          \
            ra[it] = *(const float4*)(Aptr + (size_t)(tileM + arow + it*32) * DIMC + (k0) + ac); \
        _Pragma("unroll")                                                       \
        for (int it = 0; it < 8; it++)                                          \
            rb[it] = *(const float4*)(Bmat + (size_t)((k0) + brow + it*4) * N + tileN + bc); \
    }

#define STORE_TILES(st)                                                         \
    {                                                                           \
        _Pragma("unroll")                                                       \
        for (int it = 0; it < 4; it++) {                                        \
            __half2 h0 = __floats2half2_rn(ra[it].x, ra[it].y);                 \
            __half2 h1 = __floats2half2_rn(ra[it].z, ra[it].w);                 \
            *(__half2*)&As[(size_t)(st)*BM*ALD + (arow + it*32)*ALD + ac]     = h0; \
            *(__half2*)&As[(size_t)(st)*BM*ALD + (arow + it*32)*ALD + ac + 2] = h1; \
        }                                                                       \
        _Pragma("unroll")                                                       \
        for (int it = 0; it < 8; it++) {                                        \
            __half2 h0 = __floats2half2_rn(rb[it].x, rb[it].y);                 \
            __half2 h1 = __floats2half2_rn(rb[it].z, rb[it].w);                 \
            *(__half2*)&Bs[(size_t)(st)*BK*BLD + (brow + it*4)*BLD + bc]     = h0; \
            *(__half2*)&Bs[(size_t)(st)*BK*BLD + (brow + it*4)*BLD + bc + 2] = h1; \
        }                                                                       \
    }

#define COMPUTE(st)                                                             \
    {                                                                           \
        const __half* Ab = &As[(size_t)(st) * BM * ALD];                        \
        const __half* Bb = &Bs[(size_t)(st) * BK * BLD];                        \
        _Pragma("unroll")                                                       \
        for (int ks = 0; ks < 2; ks++) {                                        \
            wmma::fragment<wmma::matrix_a, 16, 16, 16, __half, wmma::row_major> af[4]; \
            wmma::fragment<wmma::matrix_b, 16, 16, 16, __half, wmma::row_major> bf[4]; \
            _Pragma("unroll")                                                   \
            for (int i = 0; i < 4; i++)                                         \
                wmma::load_matrix_sync(af[i], Ab + (wm*64 + i*16) * ALD + ks*16, ALD); \
            _Pragma("unroll")                                                   \
            for (int j = 0; j < 4; j++)                                         \
                wmma::load_matrix_sync(bf[j], Bb + (ks*16) * BLD + wn*64 + j*16, BLD); \
            _Pragma("unroll")                                                   \
            for (int i = 0; i < 4; i++)                                         \
                _Pragma("unroll")                                               \
                for (int j = 0; j < 4; j++)                                     \
                    wmma::mma_sync(acc[i][j], af[i], bf[j], acc[i][j]);         \
        }                                                                       \
    }

    LOAD_TILES(0);
    STORE_TILES(0);
    __syncthreads();

    int cur = 0;
    for (int k0 = BK; k0 < DIMC; k0 += BK) {
        LOAD_TILES(k0);      // prefetch next tile into regs (overlaps compute)
        COMPUTE(cur);
        STORE_TILES(cur ^ 1);
        __syncthreads();
        cur ^= 1;
    }
    COMPUTE(cur);

#undef LOAD_TILES
#undef STORE_TILES
#undef COMPUTE

    if (MODE == 1) {
#pragma unroll
        for (int i = 0; i < 4; i++)
#pragma unroll
            for (int j = 0; j < 4; j++) {
                float* cptr = Cout + (size_t)(tileM + wm * 64 + i * 16) * N
                                   + tileN + wn * 64 + j * 16;
                wmma::store_matrix_sync(cptr, acc[i][j], N, wmma::mem_row_major);
            }
    } else {
        // each warp's 64-col stripe lies in one 128-col head block
        int colw  = tileN + wn * 64;
        int nb128 = colw >> 7;
        int which = nb128 >> 4;     // 0:q 1:k 2:v
        int h     = nb128 & 15;
        int cin   = colw & 127;     // 0 or 64
        int b     = tileM / SEQL;
        int t0    = tileM % SEQL;
        float* dstbase = (which == 0 ? g_q : (which == 1 ? g_k : g_v))
                       + (size_t)((b * NHEAD + h) * SEQL + t0 + wm * 64) * HDIM + cin;
#pragma unroll
        for (int i = 0; i < 4; i++)
#pragma unroll
            for (int j = 0; j < 4; j++) {
                float* cptr = dstbase + (size_t)(i * 16) * HDIM + j * 16;
                wmma::store_matrix_sync(cptr, acc[i][j], HDIM, wmma::mem_row_major);
            }
    }
}

// ---------------------------------------------------------------------------
// RoPE in-place on q and k: first 16 dims of each head, pairs (p, p+8)
// ---------------------------------------------------------------------------
__global__ void rope_kernel()
{
    int i = blockIdx.x * blockDim.x + threadIdx.x;
    const int per = BATCH * NHEAD * SEQL * 8;
    if (i >= 2 * per) return;
    int which = i / per;
    int r  = i % per;
    int bh = r / (SEQL * 8);
    int t  = (r / 8) % SEQL;
    int p  = r & 7;

    float inv = powf(10000.0f, -(float)p / 8.0f);
    float ang = (float)t * inv;
    float c = cosf(ang), s = sinf(ang);

    float* base = (which ? g_k : g_q) + (size_t)(bh * SEQL + t) * HDIM;
    float x1 = base[p];
    float x2 = base[p + 8];
    base[p]     = x1 * c - x2 * s;
    base[p + 8] = x2 * c + x1 * s;
}

// ---------------------------------------------------------------------------
// Causal flash attention, fp32 SIMT. BQ=BK=64, 256 threads. (round-5 version)
// ---------------------------------------------------------------------------
#define AQ 64
#define AK 64
#define KTLD 65   // padded ld of transposed K
#define ATTN_SMEM ((AQ*HDIM + HDIM*KTLD + AK*HDIM + AQ*AK) * 4)

__global__ void __launch_bounds__(256)
attn_kernel(float* __restrict__ Y)
{
    extern __shared__ float smattn[];
    float* Qs = smattn;                    // 64*128
    float* Kt = Qs + AQ * HDIM;            // 128*65 (transposed K)
    float* Vs = Kt + HDIM * KTLD;          // 64*128
    float* Ps = Vs + AK * HDIM;            // 64*64

    const int tid = threadIdx.x;
    const int w   = tid >> 5;
    const int l   = tid & 31;
    const int bh  = blockIdx.y;            // 0..255
    const int qblk = blockIdx.x;           // 0..7
    const float scale = 0.08838834764831845f;   // 1/sqrt(128)

    const float* Qg = g_q + (size_t)bh * SEQL * HDIM;
    const float* Kg = g_k + (size_t)bh * SEQL * HDIM;
    const float* Vg = g_v + (size_t)bh * SEQL * HDIM;

#pragma unroll
    for (int it = 0; it < 8; it++) {
        int idx = tid + it * 256;
        int row = idx >> 5;
        int c4  = idx & 31;
        float4 v = *(const float4*)(Qg + (size_t)(qblk * AQ + row) * HDIM + c4 * 4);
        v.x *= scale; v.y *= scale; v.z *= scale; v.w *= scale;
        *(float4*)&Qs[row * HDIM + c4 * 4] = v;
    }

    float o[8][4];
    float mr[8], lr[8];
#pragma unroll
    for (int r = 0; r < 8; r++) {
        mr[r] = -INFINITY; lr[r] = 0.0f;
        o[r][0] = o[r][1] = o[r][2] = o[r][3] = 0.0f;
    }

    for (int j = 0; j <= qblk; j++) {
        __syncthreads();
#pragma unroll
        for (int it = 0; it < 8; it++) {
            int idx = tid + it * 256;
            int col = idx >> 5;
            int c4  = idx & 31;
            int kk  = c4 * 4;
            float4 kv = *(const float4*)(Kg + (size_t)(j * AK + col) * HDIM + kk);
            Kt[(kk + 0) * KTLD + col] = kv.x;
            Kt[(kk + 1) * KTLD + col] = kv.y;
            Kt[(kk + 2) * KTLD + col] = kv.z;
            Kt[(kk + 3) * KTLD + col] = kv.w;
            float4 vv = *(const float4*)(Vg + (size_t)(j * AK + col) * HDIM + kk);
            *(float4*)&Vs[col * HDIM + kk] = vv;
        }
        __syncthreads();

        float s0[8], s1[8];
#pragma unroll
        for (int r = 0; r < 8; r++) { s0[r] = 0.0f; s1[r] = 0.0f; }
        for (int kk = 0; kk < HDIM; kk += 4) {
            float ka[4], kb[4];
#pragma unroll
            for (int u = 0; u < 4; u++) {
                ka[u] = Kt[(kk + u) * KTLD + l];
                kb[u] = Kt[(kk + u) * KTLD + l + 32];
            }
#pragma unroll
            for (int r = 0; r < 8; r++) {
                float4 qv = *(const float4*)&Qs[(w * 8 + r) * HDIM + kk];
                s0[r] += qv.x * ka[0] + qv.y * ka[1] + qv.z * ka[2] + qv.w * ka[3];
                s1[r] += qv.x * kb[0] + qv.y * kb[1] + qv.z * kb[2] + qv.w * kb[3];
            }
        }

        if (j == qblk) {
#pragma unroll
            for (int r = 0; r < 8; r++) {
                int row = w * 8 + r;
                if (l > row)      s0[r] = -1e30f;
                if (l + 32 > row) s1[r] = -1e30f;
            }
        }

#pragma unroll
        for (int r = 0; r < 8; r++) {
            float mx = fmaxf(s0[r], s1[r]);
#pragma unroll
            for (int off = 16; off; off >>= 1)
                mx = fmaxf(mx, __shfl_xor_sync(0xffffffffu, mx, off));
            float mnew  = fmaxf(mr[r], mx);
            float alpha = __expf(mr[r] - mnew);
            float p0 = __expf(s0[r] - mnew);
            float p1 = __expf(s1[r] - mnew);
            float rs = p0 + p1;
#pragma unroll
            for (int off = 16; off; off >>= 1)
                rs += __shfl_xor_sync(0xffffffffu, rs, off);
            lr[r] = lr[r] * alpha + rs;
            mr[r] = mnew;
            o[r][0] *= alpha; o[r][1] *= alpha; o[r][2] *= alpha; o[r][3] *= alpha;
            Ps[(w * 8 + r) * AK + l]      = p0;
            Ps[(w * 8 + r) * AK + l + 32] = p1;
        }
        __syncwarp();

        for (int col = 0; col < AK; col++) {
            float4 vv = *(const float4*)&Vs[col * HDIM + 4 * l];
#pragma unroll
            for (int r = 0; r < 8; r++) {
                float p = Ps[(w * 8 + r) * AK + col];
                o[r][0] += p * vv.x;
                o[r][1] += p * vv.y;
                o[r][2] += p * vv.z;
                o[r][3] += p * vv.w;
            }
        }
    }

    int b = bh >> 4, h = bh & 15;
#pragma unroll
    for (int r = 0; r < 8; r++) {
        float inv = 1.0f / lr[r];
        int t = qblk * AQ + w * 8 + r;
        float4 ov;
        ov.x = o[r][0] * inv; ov.y = o[r][1] * inv;
        ov.z = o[r][2] * inv; ov.w = o[r][3] * inv;
        *(float4*)(Y + (size_t)(b * SEQL + t) * DIMC + h * HDIM + 4 * l) = ov;
    }
}

// ---------------------------------------------------------------------------
extern "C" void kernel_launch(void* const* d_in, const int* in_sizes, int n_in,
                              void* d_out, int out_size)
{
    const float* x    = (const float*)d_in[0];   // [16,512,2048]
    const float* Wqkv = (const float*)d_in[1];   // [2048,6144]
    const float* Wout = (const float*)d_in[2];   // [2048,2048]
    float* out = (float*)d_out;                  // [16,512,2048]

    static bool attrs_set = false;
    if (!attrs_set) {
        cudaFuncSetAttribute(gemm_fp16_kernel<0>, cudaFuncAttributeMaxDynamicSharedMemorySize, GEMM_SMEM);
        cudaFuncSetAttribute(gemm_fp16_kernel<1>, cudaFuncAttributeMaxDynamicSharedMemorySize, GEMM_SMEM);
        cudaFuncSetAttribute(attn_kernel, cudaFuncAttributeMaxDynamicSharedMemorySize, ATTN_SMEM);
        attrs_set = true;
    }

    // 1) QKV GEMM (fp16 tensor cores) with fused scatter to [B,H,T,hd]
    gemm_fp16_kernel<0><<<dim3(NQKV / BN, MTOT / BM), 256, GEMM_SMEM>>>(x, Wqkv, nullptr, NQKV);

    // 2) RoPE on q,k (first 16 dims)
    {
        int total = 2 * BATCH * NHEAD * SEQL * 8;
        rope_kernel<<<(total + 255) / 256, 256>>>();
    }

    // 3) Causal flash attention (SIMT fp32)
    {
        float* yp = nullptr;
        cudaGetSymbolAddress((void**)&yp, g_y);
        attn_kernel<<<dim3(SEQL / AQ, BATCH * NHEAD), 256, ATTN_SMEM>>>(yp);
    }

    // 4) Output projection (fp16 tensor cores)
    gemm_fp16_kernel<1><<<dim3(DIMC / BN, MTOT / BM), 256, GEMM_SMEM>>>(nullptr, Wout, out, DIMC);
}

// round 10
// speedup vs baseline: 2.7280x; 1.1225x over previous
#include <cuda_runtime.h>
#include <mma.h>
#include <cuda_fp16.h>
#include <cmath>

using namespace nvcuda;

#define BATCH 16
#define SEQL  512
#define DIMC  2048
#define NHEAD 16
#define HDIM  128
#define NQKV  6144
#define MTOT  (BATCH*SEQL)   // 8192

// Scratch (device globals: allocation-guard safe)
__device__ float  g_q[(size_t)BATCH*NHEAD*SEQL*HDIM];   // [B,H,T,hd]
__device__ float  g_k[(size_t)BATCH*NHEAD*SEQL*HDIM];
__device__ float  g_v[(size_t)BATCH*NHEAD*SEQL*HDIM];
__device__ __half g_xh[(size_t)MTOT*DIMC];              // x in fp16
__device__ __half g_yh[(size_t)MTOT*DIMC];              // attention out in fp16
__device__ __half g_wqkvh[(size_t)DIMC*NQKV];           // Wqkv in fp16
__device__ __half g_wouth[(size_t)DIMC*DIMC];           // Wout in fp16

// ---------------------------------------------------------------------------
// fp32 -> fp16 bulk convert (8 elems/thread)
// ---------------------------------------------------------------------------
__global__ void f2h_kernel(const float* __restrict__ s, __half* __restrict__ d, int n)
{
    int i = (blockIdx.x * blockDim.x + threadIdx.x) * 8;
    if (i >= n) return;
    float4 a = *(const float4*)(s + i);
    float4 b = *(const float4*)(s + i + 4);
    __half2 h[4];
    h[0] = __floats2half2_rn(a.x, a.y);
    h[1] = __floats2half2_rn(a.z, a.w);
    h[2] = __floats2half2_rn(b.x, b.y);
    h[3] = __floats2half2_rn(b.z, b.w);
    *(uint4*)(d + i) = *(uint4*)h;
}

// ---------------------------------------------------------------------------
// FP16 GEMM (fp32 accumulate), double-buffered, 128x256 CTA, 64x64 warp tiles
// Inputs pre-converted fp16 in global. C[M,2048] x [2048,N].
// MODE 0: A = g_xh,  B = g_wqkvh, N=6144, scatter epilogue -> g_q/g_k/g_v
// MODE 1: A = g_yh,  B = g_wouth, N=2048, row-major epilogue -> Cout
// ---------------------------------------------------------------------------
#define BM 128
#define BN 256
#define BK 32
#define ALD 40     // halfs; 80B row stride
#define BLD 264    // halfs; 528B row stride
#define GEMM_SMEM ((2*BM*ALD + 2*BK*BLD) * 2)   // 54272 B

template<int MODE>
__global__ void __launch_bounds__(256, 1)
gemm_fp16_kernel(float* __restrict__ Cout, int N)
{
    extern __shared__ __half sm[];
    __half* As = sm;                       // [2][BM][ALD]
    __half* Bs = sm + 2 * BM * ALD;        // [2][BK][BLD]

    const __half* Ah = (MODE == 1) ? g_yh : g_xh;
    const __half* Bh = (MODE == 1) ? g_wouth : g_wqkvh;

    const int tid  = threadIdx.x;
    const int warp = tid >> 5;
    const int wm   = warp >> 2;      // 0..1  (rows of 64)
    const int wn   = warp & 3;       // 0..3  (cols of 64)
    const int tileM = blockIdx.y * BM;
    const int tileN = blockIdx.x * BN;

    const int arow = tid >> 2;       // 0..63 (stride 64 over 2 its)
    const int ac   = (tid & 3) * 8;  // half-index col
    const int brow = tid >> 5;       // 0..7 (stride 8 over 4 its)
    const int bc   = (tid & 31) * 8;

    wmma::fragment<wmma::accumulator, 16, 16, 16, float> acc[4][4];
#pragma unroll
    for (int i = 0; i < 4; i++)
#pragma unroll
        for (int j = 0; j < 4; j++) wmma::fill_fragment(acc[i][j], 0.0f);

    uint4 ra[2], rb[4];

#define LOAD_TILES(k0)                                                          \
    {                                                                           \
        _Pragma("unroll")                                                       \
        for (int it = 0; it < 2; it++)                                          \
            ra[it] = *(const uint4*)(Ah + (size_t)(tileM + arow + it*64) * DIMC + (k0) + ac); \
        _Pragma("unroll")                                                       \
        for (int it = 0; it < 4; it++)                                          \
            rb[it] = *(const uint4*)(Bh + (size_t)((k0) + brow + it*8) * N + tileN + bc); \
    }

#define STORE_TILES(st)                                                         \
    {                                                                           \
        _Pragma("unroll")                                                       \
        for (int it = 0; it < 2; it++)                                          \
            *(uint4*)&As[(size_t)(st)*BM*ALD + (arow + it*64)*ALD + ac] = ra[it]; \
        _Pragma("unroll")                                                       \
        for (int it = 0; it < 4; it++)                                          \
            *(uint4*)&Bs[(size_t)(st)*BK*BLD + (brow + it*8)*BLD + bc] = rb[it]; \
    }

#define COMPUTE(st)                                                             \
    {                                                                           \
        const __half* Ab = &As[(size_t)(st) * BM * ALD];                        \
        const __half* Bb = &Bs[(size_t)(st) * BK * BLD];                        \
        _Pragma("unroll")                                                       \
        for (int ks = 0; ks < 2; ks++) {                                        \
            wmma::fragment<wmma::matrix_a, 16, 16, 16, __half, wmma::row_major> af[4]; \
            wmma::fragment<wmma::matrix_b, 16, 16, 16, __half, wmma::row_major> bf[4]; \
            _Pragma("unroll")                                                   \
            for (int i = 0; i < 4; i++)                                         \
                wmma::load_matrix_sync(af[i], Ab + (wm*64 + i*16) * ALD + ks*16, ALD); \
            _Pragma("unroll")                                                   \
            for (int j = 0; j < 4; j++)                                         \
                wmma::load_matrix_sync(bf[j], Bb + (ks*16) * BLD + wn*64 + j*16, BLD); \
            _Pragma("unroll")                                                   \
            for (int i = 0; i < 4; i++)                                         \
                _Pragma("unroll")                                               \
                for (int j = 0; j < 4; j++)                                     \
                    wmma::mma_sync(acc[i][j], af[i], bf[j], acc[i][j]);         \
        }                                                                       \
    }

    LOAD_TILES(0);
    STORE_TILES(0);
    __syncthreads();

    int cur = 0;
    for (int k0 = BK; k0 < DIMC; k0 += BK) {
        LOAD_TILES(k0);      // prefetch next tile into regs (overlaps compute)
        COMPUTE(cur);
        STORE_TILES(cur ^ 1);
        __syncthreads();
        cur ^= 1;
    }
    COMPUTE(cur);

#undef LOAD_TILES
#undef STORE_TILES
#undef COMPUTE

    if (MODE == 1) {
#pragma unroll
        for (int i = 0; i < 4; i++)
#pragma unroll
            for (int j = 0; j < 4; j++) {
                float* cptr = Cout + (size_t)(tileM + wm * 64 + i * 16) * N
                                   + tileN + wn * 64 + j * 16;
                wmma::store_matrix_sync(cptr, acc[i][j], N, wmma::mem_row_major);
            }
    } else {
        // each warp's 64-col stripe lies in one 128-col head block
        int colw  = tileN + wn * 64;
        int nb128 = colw >> 7;
        int which = nb128 >> 4;     // 0:q 1:k 2:v
        int h     = nb128 & 15;
        int cin   = colw & 127;     // 0 or 64
        int b     = tileM / SEQL;
        int t0    = tileM % SEQL;
        float* dstbase = (which == 0 ? g_q : (which == 1 ? g_k : g_v))
                       + (size_t)((b * NHEAD + h) * SEQL + t0 + wm * 64) * HDIM + cin;
#pragma unroll
        for (int i = 0; i < 4; i++)
#pragma unroll
            for (int j = 0; j < 4; j++) {
                float* cptr = dstbase + (size_t)(i * 16) * HDIM + j * 16;
                wmma::store_matrix_sync(cptr, acc[i][j], HDIM, wmma::mem_row_major);
            }
    }
}

// ---------------------------------------------------------------------------
// RoPE in-place on q and k: first 16 dims of each head, pairs (p, p+8)
// ---------------------------------------------------------------------------
__global__ void rope_kernel()
{
    int i = blockIdx.x * blockDim.x + threadIdx.x;
    const int per = BATCH * NHEAD * SEQL * 8;
    if (i >= 2 * per) return;
    int which = i / per;
    int r  = i % per;
    int bh = r / (SEQL * 8);
    int t  = (r / 8) % SEQL;
    int p  = r & 7;

    float inv = powf(10000.0f, -(float)p / 8.0f);
    float ang = (float)t * inv;
    float c = cosf(ang), s = sinf(ang);

    float* base = (which ? g_k : g_q) + (size_t)(bh * SEQL + t) * HDIM;
    float x1 = base[p];
    float x2 = base[p + 8];
    base[p]     = x1 * c - x2 * s;
    base[p + 8] = x2 * c + x1 * s;
}

// ---------------------------------------------------------------------------
// Causal flash attention, fp32 SIMT. BQ=BK=64, 256 threads. (round-5 version,
// output stored as fp16 into g_yh for the fp16 output-projection GEMM)
// ---------------------------------------------------------------------------
#define AQ 64
#define AK 64
#define KTLD 65   // padded ld of transposed K
#define ATTN_SMEM ((AQ*HDIM + HDIM*KTLD + AK*HDIM + AQ*AK) * 4)

__global__ void __launch_bounds__(256)
attn_kernel()
{
    extern __shared__ float smattn[];
    float* Qs = smattn;                    // 64*128
    float* Kt = Qs + AQ * HDIM;            // 128*65 (transposed K)
    float* Vs = Kt + HDIM * KTLD;          // 64*128
    float* Ps = Vs + AK * HDIM;            // 64*64

    const int tid = threadIdx.x;
    const int w   = tid >> 5;
    const int l   = tid & 31;
    const int bh  = blockIdx.y;            // 0..255
    const int qblk = blockIdx.x;           // 0..7
    const float scale = 0.08838834764831845f;   // 1/sqrt(128)

    const float* Qg = g_q + (size_t)bh * SEQL * HDIM;
    const float* Kg = g_k + (size_t)bh * SEQL * HDIM;
    const float* Vg = g_v + (size_t)bh * SEQL * HDIM;

#pragma unroll
    for (int it = 0; it < 8; it++) {
        int idx = tid + it * 256;
        int row = idx >> 5;
        int c4  = idx & 31;
        float4 v = *(const float4*)(Qg + (size_t)(qblk * AQ + row) * HDIM + c4 * 4);
        v.x *= scale; v.y *= scale; v.z *= scale; v.w *= scale;
        *(float4*)&Qs[row * HDIM + c4 * 4] = v;
    }

    float o[8][4];
    float mr[8], lr[8];
#pragma unroll
    for (int r = 0; r < 8; r++) {
        mr[r] = -INFINITY; lr[r] = 0.0f;
        o[r][0] = o[r][1] = o[r][2] = o[r][3] = 0.0f;
    }

    for (int j = 0; j <= qblk; j++) {
        __syncthreads();
#pragma unroll
        for (int it = 0; it < 8; it++) {
            int idx = tid + it * 256;
            int col = idx >> 5;
            int c4  = idx & 31;
            int kk  = c4 * 4;
            float4 kv = *(const float4*)(Kg + (size_t)(j * AK + col) * HDIM + kk);
            Kt[(kk + 0) * KTLD + col] = kv.x;
            Kt[(kk + 1) * KTLD + col] = kv.y;
            Kt[(kk + 2) * KTLD + col] = kv.z;
            Kt[(kk + 3) * KTLD + col] = kv.w;
            float4 vv = *(const float4*)(Vg + (size_t)(j * AK + col) * HDIM + kk);
            *(float4*)&Vs[col * HDIM + kk] = vv;
        }
        __syncthreads();

        float s0[8], s1[8];
#pragma unroll
        for (int r = 0; r < 8; r++) { s0[r] = 0.0f; s1[r] = 0.0f; }
        for (int kk = 0; kk < HDIM; kk += 4) {
            float ka[4], kb[4];
#pragma unroll
            for (int u = 0; u < 4; u++) {
                ka[u] = Kt[(kk + u) * KTLD + l];
                kb[u] = Kt[(kk + u) * KTLD + l + 32];
            }
#pragma unroll
            for (int r = 0; r < 8; r++) {
                float4 qv = *(const float4*)&Qs[(w * 8 + r) * HDIM + kk];
                s0[r] += qv.x * ka[0] + qv.y * ka[1] + qv.z * ka[2] + qv.w * ka[3];
                s1[r] += qv.x * kb[0] + qv.y * kb[1] + qv.z * kb[2] + qv.w * kb[3];
            }
        }

        if (j == qblk) {
#pragma unroll
            for (int r = 0; r < 8; r++) {
                int row = w * 8 + r;
                if (l > row)      s0[r] = -1e30f;
                if (l + 32 > row) s1[r] = -1e30f;
            }
        }

#pragma unroll
        for (int r = 0; r < 8; r++) {
            float mx = fmaxf(s0[r], s1[r]);
#pragma unroll
            for (int off = 16; off; off >>= 1)
                mx = fmaxf(mx, __shfl_xor_sync(0xffffffffu, mx, off));
            float mnew  = fmaxf(mr[r], mx);
            float alpha = __expf(mr[r] - mnew);
            float p0 = __expf(s0[r] - mnew);
            float p1 = __expf(s1[r] - mnew);
            float rs = p0 + p1;
#pragma unroll
            for (int off = 16; off; off >>= 1)
                rs += __shfl_xor_sync(0xffffffffu, rs, off);
            lr[r] = lr[r] * alpha + rs;
            mr[r] = mnew;
            o[r][0] *= alpha; o[r][1] *= alpha; o[r][2] *= alpha; o[r][3] *= alpha;
            Ps[(w * 8 + r) * AK + l]      = p0;
            Ps[(w * 8 + r) * AK + l + 32] = p1;
        }
        __syncwarp();

        for (int col = 0; col < AK; col++) {
            float4 vv = *(const float4*)&Vs[col * HDIM + 4 * l];
#pragma unroll
            for (int r = 0; r < 8; r++) {
                float p = Ps[(w * 8 + r) * AK + col];
                o[r][0] += p * vv.x;
                o[r][1] += p * vv.y;
                o[r][2] += p * vv.z;
                o[r][3] += p * vv.w;
            }
        }
    }

    int b = bh >> 4, h = bh & 15;
#pragma unroll
    for (int r = 0; r < 8; r++) {
        float inv = 1.0f / lr[r];
        int t = qblk * AQ + w * 8 + r;
        __half2 h0 = __floats2half2_rn(o[r][0] * inv, o[r][1] * inv);
        __half2 h1 = __floats2half2_rn(o[r][2] * inv, o[r][3] * inv);
        __half* dst = g_yh + (size_t)(b * SEQL + t) * DIMC + h * HDIM + 4 * l;
        *(__half2*)(dst)     = h0;
        *(__half2*)(dst + 2) = h1;
    }
}

// ---------------------------------------------------------------------------
extern "C" void kernel_launch(void* const* d_in, const int* in_sizes, int n_in,
                              void* d_out, int out_size)
{
    const float* x    = (const float*)d_in[0];   // [16,512,2048]
    const float* Wqkv = (const float*)d_in[1];   // [2048,6144]
    const float* Wout = (const float*)d_in[2];   // [2048,2048]
    float* out = (float*)d_out;                  // [16,512,2048]

    static bool attrs_set = false;
    static __half *xh = nullptr, *wqkvh = nullptr, *wouth = nullptr;
    if (!attrs_set) {
        cudaFuncSetAttribute(gemm_fp16_kernel<0>, cudaFuncAttributeMaxDynamicSharedMemorySize, GEMM_SMEM);
        cudaFuncSetAttribute(gemm_fp16_kernel<1>, cudaFuncAttributeMaxDynamicSharedMemorySize, GEMM_SMEM);
        cudaFuncSetAttribute(attn_kernel, cudaFuncAttributeMaxDynamicSharedMemorySize, ATTN_SMEM);
        cudaGetSymbolAddress((void**)&xh,    g_xh);
        cudaGetSymbolAddress((void**)&wqkvh, g_wqkvh);
        cudaGetSymbolAddress((void**)&wouth, g_wouth);
        attrs_set = true;
    }

    // 0) Convert inputs to fp16 once
    {
        int n0 = MTOT * DIMC;        // x
        int n1 = DIMC * NQKV;        // Wqkv
        int n2 = DIMC * DIMC;        // Wout
        f2h_kernel<<<n0 / (256*8), 256>>>(x,    xh,    n0);
        f2h_kernel<<<n1 / (256*8), 256>>>(Wqkv, wqkvh, n1);
        f2h_kernel<<<n2 / (256*8), 256>>>(Wout, wouth, n2);
    }

    // 1) QKV GEMM (fp16 tensor cores) with fused scatter to [B,H,T,hd]
    gemm_fp16_kernel<0><<<dim3(NQKV / BN, MTOT / BM), 256, GEMM_SMEM>>>(nullptr, NQKV);

    // 2) RoPE on q,k (first 16 dims)
    {
        int total = 2 * BATCH * NHEAD * SEQL * 8;
        rope_kernel<<<(total + 255) / 256, 256>>>();
    }

    // 3) Causal flash attention (SIMT fp32, fp16 output)
    attn_kernel<<<dim3(SEQL / AQ, BATCH * NHEAD), 256, ATTN_SMEM>>>();

    // 4) Output projection (fp16 tensor cores)
    gemm_fp16_kernel<1><<<dim3(DIMC / BN, MTOT / BM), 256, GEMM_SMEM>>>(out, DIMC);
}

// round 13
// speedup vs baseline: 3.9492x; 1.4476x over previous
#include <cuda_runtime.h>
#include <mma.h>
#include <cuda_fp16.h>
#include <cstdint>
#include <cmath>

using namespace nvcuda;

#define BATCH 16
#define SEQL  512
#define DIMC  2048
#define NHEAD 16
#define HDIM  128
#define NQKV  6144
#define MTOT  (BATCH*SEQL)   // 8192

// Scratch (device globals: allocation-guard safe)
__device__ float  g_q[(size_t)BATCH*NHEAD*SEQL*HDIM];   // fp32 from gemm0
__device__ float  g_k[(size_t)BATCH*NHEAD*SEQL*HDIM];
__device__ float  g_v[(size_t)BATCH*NHEAD*SEQL*HDIM];
__device__ __half g_qh[(size_t)BATCH*NHEAD*SEQL*HDIM];  // rope+scale, fp16
__device__ __half g_kh[(size_t)BATCH*NHEAD*SEQL*HDIM];  // rope, fp16
__device__ __half g_vh[(size_t)BATCH*NHEAD*SEQL*HDIM];  // fp16
__device__ __half g_xh[(size_t)MTOT*DIMC];
__device__ __half g_yh[(size_t)MTOT*DIMC];
__device__ __half g_wqkvh[(size_t)DIMC*NQKV];
__device__ __half g_wouth[(size_t)DIMC*DIMC];

__device__ __forceinline__ uint32_t smem_u32(const void* p) {
    uint32_t a;
    asm("{ .reg .u64 t; cvta.to.shared.u64 t, %1; cvt.u32.u64 %0, t; }" : "=r"(a) : "l"(p));
    return a;
}

// FMA-pipe exp (avoids MUFU). x <= 0 expected; handles -inf/-1e30 via clamp.
__device__ __forceinline__ float fexp(float x) {
    x = fmaxf(x, -87.0f);
    float t  = fmaf(x, 1.4426950408889634f, 12582912.0f);
    float ki = t - 12582912.0f;                     // round(x*log2e)
    float f  = fmaf(x, 1.4426950408889634f, -ki);   // frac in [-0.5,0.5]
    float p = 0.0013333558f;
    p = fmaf(p, f, 0.0096181291f);
    p = fmaf(p, f, 0.0555041087f);
    p = fmaf(p, f, 0.2402265069f);
    p = fmaf(p, f, 0.6931471806f);
    p = fmaf(p, f, 1.0f);
    return p * __int_as_float(((int)ki + 127) << 23);
}

// ---------------------------------------------------------------------------
// fp32 -> fp16 bulk convert
// ---------------------------------------------------------------------------
__global__ void f2h_kernel(const float* __restrict__ s, __half* __restrict__ d, int n)
{
    int i = (blockIdx.x * blockDim.x + threadIdx.x) * 8;
    if (i >= n) return;
    float4 a = *(const float4*)(s + i);
    float4 b = *(const float4*)(s + i + 4);
    __half2 h[4];
    h[0] = __floats2half2_rn(a.x, a.y);
    h[1] = __floats2half2_rn(a.z, a.w);
    h[2] = __floats2half2_rn(b.x, b.y);
    h[3] = __floats2half2_rn(b.z, b.w);
    *(uint4*)(d + i) = *(uint4*)h;
}

// ---------------------------------------------------------------------------
// rope (first 16 dims) + scale + fp32->fp16; thread = (row, group of 16 dims)
// ---------------------------------------------------------------------------
__global__ void ropeconv_kernel(const float* __restrict__ s, __half* __restrict__ d,
                                float scale)
{
    int i = blockIdx.x * blockDim.x + threadIdx.x;
    int row = i >> 3, g16 = i & 7;
    int t = row & (SEQL - 1);
    const float* sp = s + (size_t)row * HDIM + g16 * 16;
    __half* dp = d + (size_t)row * HDIM + g16 * 16;
    float v[16];
    *(float4*)(v + 0)  = *(const float4*)(sp + 0);
    *(float4*)(v + 4)  = *(const float4*)(sp + 4);
    *(float4*)(v + 8)  = *(const float4*)(sp + 8);
    *(float4*)(v + 12) = *(const float4*)(sp + 12);
    if (g16 == 0) {
#pragma unroll
        for (int p = 0; p < 8; p++) {
            float inv = powf(10000.0f, -(float)p * 0.125f);
            float ang = (float)t * inv;
            float c = cosf(ang), sn = sinf(ang);
            float x1 = v[p], x2 = v[p + 8];
            v[p]     = x1 * c - x2 * sn;
            v[p + 8] = x2 * c + x1 * sn;
        }
    }
    __half2 h[8];
#pragma unroll
    for (int j = 0; j < 8; j++)
        h[j] = __floats2half2_rn(v[2*j] * scale, v[2*j+1] * scale);
    *(uint4*)(dp + 0) = *(uint4*)(h + 0);
    *(uint4*)(dp + 8) = *(uint4*)(h + 4);
}

// ---------------------------------------------------------------------------
// FP16 GEMM (fp32 accumulate), double-buffered, 128x256 CTA, 64x64 warp tiles
// MODE 0: A=g_xh, B=g_wqkvh, N=6144, scatter epilogue -> g_q/g_k/g_v (fp32)
// MODE 1: A=g_yh, B=g_wouth, N=2048, row-major epilogue -> Cout
// ---------------------------------------------------------------------------
#define BM 128
#define BN 256
#define BK 32
#define ALD 40
#define BLD 264
#define GEMM_SMEM ((2*BM*ALD + 2*BK*BLD) * 2)   // 54272 B

template<int MODE>
__global__ void __launch_bounds__(256, 1)
gemm_fp16_kernel(float* __restrict__ Cout, int N)
{
    extern __shared__ __half sm[];
    __half* As = sm;
    __half* Bs = sm + 2 * BM * ALD;

    const __half* Ah = (MODE == 1) ? g_yh : g_xh;
    const __half* Bh = (MODE == 1) ? g_wouth : g_wqkvh;

    const int tid  = threadIdx.x;
    const int warp = tid >> 5;
    const int wm   = warp >> 2;
    const int wn   = warp & 3;
    const int tileM = blockIdx.y * BM;
    const int tileN = blockIdx.x * BN;

    const int arow = tid >> 2;
    const int ac   = (tid & 3) * 8;
    const int brow = tid >> 5;
    const int bc   = (tid & 31) * 8;

    wmma::fragment<wmma::accumulator, 16, 16, 16, float> acc[4][4];
#pragma unroll
    for (int i = 0; i < 4; i++)
#pragma unroll
        for (int j = 0; j < 4; j++) wmma::fill_fragment(acc[i][j], 0.0f);

    uint4 ra[2], rb[4];

#define LOAD_TILES(k0)                                                          \
    {                                                                           \
        _Pragma("unroll")                                                       \
        for (int it = 0; it < 2; it++)                                          \
            ra[it] = *(const uint4*)(Ah + (size_t)(tileM + arow + it*64) * DIMC + (k0) + ac); \
        _Pragma("unroll")                                                       \
        for (int it = 0; it < 4; it++)                                          \
            rb[it] = *(const uint4*)(Bh + (size_t)((k0) + brow + it*8) * N + tileN + bc); \
    }

#define STORE_TILES(st)                                                         \
    {                                                                           \
        _Pragma("unroll")                                                       \
        for (int it = 0; it < 2; it++)                                          \
            *(uint4*)&As[(size_t)(st)*BM*ALD + (arow + it*64)*ALD + ac] = ra[it]; \
        _Pragma("unroll")                                                       \
        for (int it = 0; it < 4; it++)                                          \
            *(uint4*)&Bs[(size_t)(st)*BK*BLD + (brow + it*8)*BLD + bc] = rb[it]; \
    }

#define COMPUTE(st)                                                             \
    {                                                                           \
        const __half* Ab = &As[(size_t)(st) * BM * ALD];                        \
        const __half* Bb = &Bs[(size_t)(st) * BK * BLD];                        \
        _Pragma("unroll")                                                       \
        for (int ks = 0; ks < 2; ks++) {                                        \
            wmma::fragment<wmma::matrix_a, 16, 16, 16, __half, wmma::row_major> af[4]; \
            wmma::fragment<wmma::matrix_b, 16, 16, 16, __half, wmma::row_major> bf[4]; \
            _Pragma("unroll")                                                   \
            for (int i = 0; i < 4; i++)                                         \
                wmma::load_matrix_sync(af[i], Ab + (wm*64 + i*16) * ALD + ks*16, ALD); \
            _Pragma("unroll")                                                   \
            for (int j = 0; j < 4; j++)                                         \
                wmma::load_matrix_sync(bf[j], Bb + (ks*16) * BLD + wn*64 + j*16, BLD); \
            _Pragma("unroll")                                                   \
            for (int i = 0; i < 4; i++)                                         \
                _Pragma("unroll")                                               \
                for (int j = 0; j < 4; j++)                                     \
                    wmma::mma_sync(acc[i][j], af[i], bf[j], acc[i][j]);         \
        }                                                                       \
    }

    LOAD_TILES(0);
    STORE_TILES(0);
    __syncthreads();

    int cur = 0;
    for (int k0 = BK; k0 < DIMC; k0 += BK) {
        LOAD_TILES(k0);
        COMPUTE(cur);
        STORE_TILES(cur ^ 1);
        __syncthreads();
        cur ^= 1;
    }
    COMPUTE(cur);

#undef LOAD_TILES
#undef STORE_TILES
#undef COMPUTE

    if (MODE == 1) {
#pragma unroll
        for (int i = 0; i < 4; i++)
#pragma unroll
            for (int j = 0; j < 4; j++) {
                float* cptr = Cout + (size_t)(tileM + wm * 64 + i * 16) * N
                                   + tileN + wn * 64 + j * 16;
                wmma::store_matrix_sync(cptr, acc[i][j], N, wmma::mem_row_major);
            }
    } else {
        int colw  = tileN + wn * 64;
        int nb128 = colw >> 7;
        int which = nb128 >> 4;
        int h     = nb128 & 15;
        int cin   = colw & 127;
        int b     = tileM / SEQL;
        int t0    = tileM % SEQL;
        float* dstbase = (which == 0 ? g_q : (which == 1 ? g_k : g_v))
                       + (size_t)((b * NHEAD + h) * SEQL + t0 + wm * 64) * HDIM + cin;
#pragma unroll
        for (int i = 0; i < 4; i++)
#pragma unroll
            for (int j = 0; j < 4; j++) {
                float* cptr = dstbase + (size_t)(i * 16) * HDIM + j * 16;
                wmma::store_matrix_sync(cptr, acc[i][j], HDIM, wmma::mem_row_major);
            }
    }
}

// ---------------------------------------------------------------------------
// Tensor-core flash attention (mma.sync m16n8k16, fp16 in, fp32 accum)
// BQ=128 (8 warps x 16 rows), BKV=64, cp.async double-buffered K/V.
// ---------------------------------------------------------------------------
#define KROW 136                       // halfs per smem row (272B, ldsm conflict-free)
#define QS_BYTES (128*KROW*2)          // 34816
#define KV_STG   (64*KROW*2)           // 17408
#define KS_OFF   QS_BYTES
#define VS_OFF   (KS_OFF + 2*KV_STG)
#define ATTN_SMEM (VS_OFF + 2*KV_STG)  // 104448

#define LDSM4(r0,r1,r2,r3,addr) \
    asm volatile("ldmatrix.sync.aligned.m8n8.x4.shared.b16 {%0,%1,%2,%3}, [%4];" \
        : "=r"(r0),"=r"(r1),"=r"(r2),"=r"(r3) : "r"(addr))
#define LDSM4T(r0,r1,r2,r3,addr) \
    asm volatile("ldmatrix.sync.aligned.m8n8.x4.trans.shared.b16 {%0,%1,%2,%3}, [%4];" \
        : "=r"(r0),"=r"(r1),"=r"(r2),"=r"(r3) : "r"(addr))
#define MMA16816(d,a,b0,b1) \
    asm volatile("mma.sync.aligned.m16n8k16.row.col.f32.f16.f16.f32 " \
        "{%0,%1,%2,%3},{%4,%5,%6,%7},{%8,%9},{%0,%1,%2,%3};" \
        : "+f"((d)[0]),"+f"((d)[1]),"+f"((d)[2]),"+f"((d)[3]) \
        : "r"((a)[0]),"r"((a)[1]),"r"((a)[2]),"r"((a)[3]), "r"(b0),"r"(b1))
#define CPASYNC16(saddr, gptr) \
    asm volatile("cp.async.cg.shared.global [%0], [%1], 16;" :: "r"(saddr), "l"(gptr))

__global__ void __launch_bounds__(256, 1)
attn_mma_kernel()
{
    extern __shared__ __half smh[];
    const uint32_t sb = smem_u32(smh);
    const int tid  = threadIdx.x;
    const int w    = tid >> 5;
    const int lane = tid & 31;
    const int g    = lane >> 2;
    const int tig  = lane & 3;
    const int qb   = blockIdx.x;       // 0..3
    const int bh   = blockIdx.y;       // 0..255

    const __half* Qg = g_qh + ((size_t)bh * SEQL + qb * 128) * HDIM;
    const __half* Kg = g_kh + (size_t)bh * SEQL * HDIM;
    const __half* Vg = g_vh + (size_t)bh * SEQL * HDIM;

    // stage Q (128 x 128 halfs)
#pragma unroll
    for (int it = 0; it < 8; it++) {
        int idx = tid + it * 256;      // 0..2047
        int row = idx >> 4, c = idx & 15;
        *(uint4*)(smh + row * KROW + c * 8) = *(const uint4*)(Qg + row * HDIM + c * 8);
    }

    const int nch = 2 * qb + 2;
    auto kv_load = [&](int j, int stg) {
#pragma unroll
        for (int it = 0; it < 4; it++) {
            int idx = tid + it * 256;  // 0..1023
            int row = idx >> 4, c = idx & 15;
            uint32_t off = (uint32_t)(row * KROW + c * 8) * 2;
            const size_t goff = (size_t)(j * 64 + row) * HDIM + c * 8;
            CPASYNC16(sb + KS_OFF + stg * KV_STG + off, Kg + goff);
            CPASYNC16(sb + VS_OFF + stg * KV_STG + off, Vg + goff);
        }
        asm volatile("cp.async.commit_group;");
    };
    kv_load(0, 0);
    __syncthreads();   // Q staged

    // Q fragments (register-resident for whole CTA)
    uint32_t qf[8][4];
    {
        uint32_t qbase = sb + (uint32_t)((w * 16 + (lane & 7) + ((lane >> 3) & 1) * 8) * KROW) * 2;
        int coff = ((lane >> 4) & 1) * 8;
#pragma unroll
        for (int kk = 0; kk < 8; kk++)
            LDSM4(qf[kk][0], qf[kk][1], qf[kk][2], qf[kk][3],
                  qbase + (uint32_t)(kk * 16 + coff) * 2);
    }

    float o[16][4];
#pragma unroll
    for (int n = 0; n < 16; n++) { o[n][0]=0; o[n][1]=0; o[n][2]=0; o[n][3]=0; }
    float mr0 = -1e30f, mr1 = -1e30f, lr0 = 0.0f, lr1 = 0.0f;

    const int krow_off = (lane & 7) + ((lane >> 4) & 1) * 8;   // K ldsm row pattern
    const int kcol_off = ((lane >> 3) & 1) * 8;
    const int vrow_off = (lane & 7) + ((lane >> 3) & 1) * 8;   // V ldsm row pattern
    const int vcol_off = ((lane >> 4) & 1) * 8;

    for (int j = 0; j < nch; j++) {
        int stg = j & 1;
        if (j + 1 < nch) {
            kv_load(j + 1, stg ^ 1);
            asm volatile("cp.async.wait_group 1;" ::: "memory");
        } else {
            asm volatile("cp.async.wait_group 0;" ::: "memory");
        }
        __syncthreads();

        bool skipw = (j == 2 * qb + 1) && (w < 4);   // chunk entirely in future
        if (!skipw) {
            // --- S = Q K^T : 8 n-tiles x 4 regs ---
            float s[8][4];
#pragma unroll
            for (int n = 0; n < 8; n++) { s[n][0]=0; s[n][1]=0; s[n][2]=0; s[n][3]=0; }
            uint32_t kbase = sb + KS_OFF + stg * KV_STG;
#pragma unroll
            for (int kk = 0; kk < 8; kk++) {
#pragma unroll
                for (int p = 0; p < 4; p++) {
                    uint32_t addr = kbase +
                        (uint32_t)((p * 16 + krow_off) * KROW + kk * 16 + kcol_off) * 2;
                    uint32_t b0, b1, b2, b3;
                    LDSM4(b0, b1, b2, b3, addr);
                    MMA16816(s[2*p],   qf[kk], b0, b1);
                    MMA16816(s[2*p+1], qf[kk], b2, b3);
                }
            }

            // --- causal mask (only on diagonal chunks) ---
            int qrow0 = qb * 128 + w * 16 + g;
            bool need_mask = (j == 2 * qb && w < 4) || (j == 2 * qb + 1 && w >= 4);
            if (need_mask) {
#pragma unroll
                for (int n = 0; n < 8; n++) {
                    int key = j * 64 + n * 8 + 2 * tig;
                    if (key     > qrow0)     s[n][0] = -1e30f;
                    if (key + 1 > qrow0)     s[n][1] = -1e30f;
                    if (key     > qrow0 + 8) s[n][2] = -1e30f;
                    if (key + 1 > qrow0 + 8) s[n][3] = -1e30f;
                }
            }

            // --- online softmax (rows g, g+8; quad reduction) ---
            float mx0 = -1e30f, mx1 = -1e30f;
#pragma unroll
            for (int n = 0; n < 8; n++) {
                mx0 = fmaxf(mx0, fmaxf(s[n][0], s[n][1]));
                mx1 = fmaxf(mx1, fmaxf(s[n][2], s[n][3]));
            }
            mx0 = fmaxf(mx0, __shfl_xor_sync(0xffffffffu, mx0, 1));
            mx0 = fmaxf(mx0, __shfl_xor_sync(0xffffffffu, mx0, 2));
            mx1 = fmaxf(mx1, __shfl_xor_sync(0xffffffffu, mx1, 1));
            mx1 = fmaxf(mx1, __shfl_xor_sync(0xffffffffu, mx1, 2));
            float mn0 = fmaxf(mr0, mx0), mn1 = fmaxf(mr1, mx1);
            float al0 = fexp(mr0 - mn0), al1 = fexp(mr1 - mn1);
            float p[8][4];
            float rs0 = 0.0f, rs1 = 0.0f;
#pragma unroll
            for (int n = 0; n < 8; n++) {
                p[n][0] = fexp(s[n][0] - mn0);
                p[n][1] = fexp(s[n][1] - mn0);
                p[n][2] = fexp(s[n][2] - mn1);
                p[n][3] = fexp(s[n][3] - mn1);
                rs0 += p[n][0] + p[n][1];
                rs1 += p[n][2] + p[n][3];
            }
            rs0 += __shfl_xor_sync(0xffffffffu, rs0, 1);
            rs0 += __shfl_xor_sync(0xffffffffu, rs0, 2);
            rs1 += __shfl_xor_sync(0xffffffffu, rs1, 1);
            rs1 += __shfl_xor_sync(0xffffffffu, rs1, 2);
            lr0 = lr0 * al0 + rs0;  lr1 = lr1 * al1 + rs1;
            mr0 = mn0;  mr1 = mn1;
#pragma unroll
            for (int n = 0; n < 16; n++) {
                o[n][0] *= al0; o[n][1] *= al0;
                o[n][2] *= al1; o[n][3] *= al1;
            }

            // --- P -> A-fragments (pure register repack) ---
            uint32_t pf[4][4];
#pragma unroll
            for (int kc = 0; kc < 4; kc++) {
                __half2 h0 = __floats2half2_rn(p[2*kc][0],   p[2*kc][1]);
                __half2 h1 = __floats2half2_rn(p[2*kc][2],   p[2*kc][3]);
                __half2 h2 = __floats2half2_rn(p[2*kc+1][0], p[2*kc+1][1]);
                __half2 h3 = __floats2half2_rn(p[2*kc+1][2], p[2*kc+1][3]);
                pf[kc][0] = *(uint32_t*)&h0;
                pf[kc][1] = *(uint32_t*)&h1;
                pf[kc][2] = *(uint32_t*)&h2;
                pf[kc][3] = *(uint32_t*)&h3;
            }

            // --- O += P V ---
            uint32_t vbase = sb + VS_OFF + stg * KV_STG;
#pragma unroll
            for (int kc = 0; kc < 4; kc++) {
#pragma unroll
                for (int np = 0; np < 8; np++) {
                    uint32_t addr = vbase +
                        (uint32_t)((kc * 16 + vrow_off) * KROW + np * 16 + vcol_off) * 2;
                    uint32_t v0, v1, v2, v3;
                    LDSM4T(v0, v1, v2, v3, addr);
                    MMA16816(o[2*np],   pf[kc], v0, v1);
                    MMA16816(o[2*np+1], pf[kc], v2, v3);
                }
            }
        }
        __syncthreads();
    }

    // --- normalize + store fp16 ---
    float i0 = 1.0f / lr0, i1 = 1.0f / lr1;
    int b = bh >> 4, h = bh & 15;
    int t0 = qb * 128 + w * 16 + g;
    __half* dst0 = g_yh + (size_t)(b * SEQL + t0) * DIMC + h * HDIM + 2 * tig;
    __half* dst1 = dst0 + (size_t)8 * DIMC;
#pragma unroll
    for (int n = 0; n < 16; n++) {
        __half2 h0 = __floats2half2_rn(o[n][0] * i0, o[n][1] * i0);
        __half2 h1 = __floats2half2_rn(o[n][2] * i1, o[n][3] * i1);
        *(__half2*)(dst0 + n * 8) = h0;
        *(__half2*)(dst1 + n * 8) = h1;
    }
}

// ---------------------------------------------------------------------------
extern "C" void kernel_launch(void* const* d_in, const int* in_sizes, int n_in,
                              void* d_out, int out_size)
{
    const float* x    = (const float*)d_in[0];
    const float* Wqkv = (const float*)d_in[1];
    const float* Wout = (const float*)d_in[2];
    float* out = (float*)d_out;

    static bool init_done = false;
    static __half *xh, *wqkvh, *wouth, *qh, *kh, *vh;
    static float *qf, *kf, *vf;
    if (!init_done) {
        cudaFuncSetAttribute(gemm_fp16_kernel<0>, cudaFuncAttributeMaxDynamicSharedMemorySize, GEMM_SMEM);
        cudaFuncSetAttribute(gemm_fp16_kernel<1>, cudaFuncAttributeMaxDynamicSharedMemorySize, GEMM_SMEM);
        cudaFuncSetAttribute(attn_mma_kernel, cudaFuncAttributeMaxDynamicSharedMemorySize, ATTN_SMEM);
        cudaGetSymbolAddress((void**)&xh,    g_xh);
        cudaGetSymbolAddress((void**)&wqkvh, g_wqkvh);
        cudaGetSymbolAddress((void**)&wouth, g_wouth);
        cudaGetSymbolAddress((void**)&qh, g_qh);
        cudaGetSymbolAddress((void**)&kh, g_kh);
        cudaGetSymbolAddress((void**)&vh, g_vh);
        cudaGetSymbolAddress((void**)&qf, g_q);
        cudaGetSymbolAddress((void**)&kf, g_k);
        cudaGetSymbolAddress((void**)&vf, g_v);
        init_done = true;
    }

    // 0) inputs -> fp16
    {
        int n0 = MTOT * DIMC, n1 = DIMC * NQKV, n2 = DIMC * DIMC;
        f2h_kernel<<<n0 / 2048, 256>>>(x,    xh,    n0);
        f2h_kernel<<<n1 / 2048, 256>>>(Wqkv, wqkvh, n1);
        f2h_kernel<<<n2 / 2048, 256>>>(Wout, wouth, n2);
    }

    // 1) QKV GEMM -> g_q/g_k/g_v (fp32, [B,H,T,hd])
    gemm_fp16_kernel<0><<<dim3(NQKV / BN, MTOT / BM), 256, GEMM_SMEM>>>(nullptr, NQKV);

    // 2) rope+scale+convert q, rope+convert k, convert v
    {
        int rthreads = BATCH * NHEAD * SEQL * 8;   // 1M
        ropeconv_kernel<<<rthreads / 256, 256>>>(qf, qh, 0.08838834764831845f);
        ropeconv_kernel<<<rthreads / 256, 256>>>(kf, kh, 1.0f);
        int nv = BATCH * NHEAD * SEQL * HDIM;
        f2h_kernel<<<nv / 2048, 256>>>(vf, vh, nv);
    }

    // 3) tensor-core flash attention -> g_yh (fp16)
    attn_mma_kernel<<<dim3(4, BATCH * NHEAD), 256, ATTN_SMEM>>>();

    // 4) output projection
    gemm_fp16_kernel<1><<<dim3(DIMC / BN, MTOT / BM), 256, GEMM_SMEM>>>(out, DIMC);
}